// round 1
// baseline (speedup 1.0000x reference)
#include <cuda_runtime.h>
#include <math.h>
#include <float.h>

// Problem constants
#define B_     16
#define C_     384
#define HEADS_ 6
#define D_     64          // C_/HEADS_
#define N_     1024        // H*W = 32*32
#define O3C    1152        // 3*C_

// Scratch: qkv[b][o][n], o in [0,3C): rows [0,C)=Q, [C,2C)=K, [2C,3C)=V
__device__ float g_qkv[B_ * O3C * N_];
__device__ int g_mask_mode;   // 0 = uint8 bool, 1 = int32, 2 = float32

// ---------------------------------------------------------------------------
// Mask dtype detection.
// u8 bool  : bytes in {0,1}, ones at arbitrary byte offsets
// int32 0/1: bytes in {0,1}, ones ONLY at offset % 4 == 0
// float32  : 1.0f = 00 00 80 3F -> contains bytes > 1
// ---------------------------------------------------------------------------
__global__ void detect_mask_kernel(const unsigned char* __restrict__ m) {
    __shared__ int s_off4, s_gt1;
    if (threadIdx.x == 0) { s_off4 = 0; s_gt1 = 0; }
    __syncthreads();
    for (int i = threadIdx.x; i < 65536; i += blockDim.x) {
        unsigned char v = m[i];
        if (v != 0 && (i & 3) != 0) atomicOr(&s_off4, 1);
        if (v > 1)                  atomicOr(&s_gt1, 1);
    }
    __syncthreads();
    if (threadIdx.x == 0) {
        g_mask_mode = s_gt1 ? 2 : (s_off4 ? 0 : 1);
    }
}

// ---------------------------------------------------------------------------
// QKV GEMM: qkv[b][o][n] = sum_c w[o][c] * x[b][c][n]
// Block: 256 threads (16x16), tile 64(o) x 64(n), BK=32. 4x4 micro-tile.
// grid = (N/64, 3C/64, B) = (16, 18, 16)
// ---------------------------------------------------------------------------
__global__ __launch_bounds__(256) void qkv_gemm_kernel(
    const float* __restrict__ x, const float* __restrict__ w)
{
    __shared__ float Ws[64][33];   // [o_local][c_local]
    __shared__ float Xs[32][65];   // [c_local][n_local]

    const int b  = blockIdx.z;
    const int o0 = blockIdx.y * 64;
    const int n0 = blockIdx.x * 64;
    const int tx = threadIdx.x, ty = threadIdx.y;
    const int tid = ty * 16 + tx;

    const float* xb = x + b * C_ * N_;

    float acc[4][4];
    #pragma unroll
    for (int i = 0; i < 4; i++)
        #pragma unroll
        for (int j = 0; j < 4; j++) acc[i][j] = 0.f;

    for (int c0 = 0; c0 < C_; c0 += 32) {
        // W tile: 64 x 32
        #pragma unroll
        for (int e = tid; e < 64 * 32; e += 256) {
            int r = e >> 5, cc = e & 31;
            Ws[r][cc] = w[(o0 + r) * C_ + c0 + cc];
        }
        // X tile: 32 x 64 (coalesced over n)
        #pragma unroll
        for (int e = tid; e < 32 * 64; e += 256) {
            int r = e >> 6, nn = e & 63;
            Xs[r][nn] = xb[(c0 + r) * N_ + n0 + nn];
        }
        __syncthreads();

        #pragma unroll
        for (int kk = 0; kk < 32; ++kk) {
            float a0 = Ws[4 * ty + 0][kk];
            float a1 = Ws[4 * ty + 1][kk];
            float a2 = Ws[4 * ty + 2][kk];
            float a3 = Ws[4 * ty + 3][kk];
            float b0 = Xs[kk][4 * tx + 0];
            float b1 = Xs[kk][4 * tx + 1];
            float b2 = Xs[kk][4 * tx + 2];
            float b3 = Xs[kk][4 * tx + 3];
            acc[0][0] += a0 * b0; acc[0][1] += a0 * b1; acc[0][2] += a0 * b2; acc[0][3] += a0 * b3;
            acc[1][0] += a1 * b0; acc[1][1] += a1 * b1; acc[1][2] += a1 * b2; acc[1][3] += a1 * b3;
            acc[2][0] += a2 * b0; acc[2][1] += a2 * b1; acc[2][2] += a2 * b2; acc[2][3] += a2 * b3;
            acc[3][0] += a3 * b0; acc[3][1] += a3 * b1; acc[3][2] += a3 * b2; acc[3][3] += a3 * b3;
        }
        __syncthreads();
    }

    float* outb = g_qkv + b * O3C * N_;
    #pragma unroll
    for (int i = 0; i < 4; i++)
        #pragma unroll
        for (int j = 0; j < 4; j++)
            outb[(o0 + 4 * ty + i) * N_ + n0 + 4 * tx + j] = acc[i][j];
}

// ---------------------------------------------------------------------------
// Fused attention: per (b, h, 64-query tile). Online-softmax flash style.
// 256 threads (16x16). TQ=64, TK=32, D=64.
// Thread (ty,tx): S micro-tile 4 rows x 2 cols; O micro-tile 4 rows x 4 cols.
// Row group = 16 threads sharing ty (a half-warp) -> shfl width-16 reductions.
// grid = (16, 6, 16) = (qtile, head, batch)
// ---------------------------------------------------------------------------
__global__ __launch_bounds__(256) void attn_kernel(
    const unsigned char* __restrict__ mask_raw, float* __restrict__ out)
{
    __shared__ float Qs[64][65];   // [q_row][d]
    __shared__ float Ks[64][33];   // [d][k_col]
    __shared__ float Vs[32][65];   // [k_col][d]
    __shared__ float Ps[64][33];   // [q_row][k_col]

    const int q0 = blockIdx.x * 64;
    const int h  = blockIdx.y;
    const int b  = blockIdx.z;
    const int tx = threadIdx.x, ty = threadIdx.y;
    const int tid = ty * 16 + tx;
    const int mode = g_mask_mode;

    const float scale = rsqrtf((float)C_);    // C^{-0.5} per reference

    const float* qb = g_qkv + (b * O3C + h * D_) * N_;
    const float* kb = qb + C_ * N_;
    const float* vb = qb + 2 * C_ * N_;

    const int* mask_i32   = (const int*)mask_raw;
    const float* mask_f32 = (const float*)mask_raw;
    const int mrow0 = ((b * HEADS_ + h) * N_ + q0) * N_;   // fits in int (<2^31)

    // Load Q tile [64 rows x 64 d] (coalesced reads over n)
    #pragma unroll
    for (int e = tid; e < 64 * 64; e += 256) {
        int dd = e >> 6, r = e & 63;
        Qs[r][dd] = qb[dd * N_ + q0 + r];
    }

    float o_acc[4][4];
    float m_i[4], l_i[4];
    #pragma unroll
    for (int i = 0; i < 4; i++) {
        m_i[i] = -0.5f * FLT_MAX;
        l_i[i] = 0.f;
        #pragma unroll
        for (int j = 0; j < 4; j++) o_acc[i][j] = 0.f;
    }

    for (int k0 = 0; k0 < N_; k0 += 32) {
        __syncthreads();   // prev PV done before overwriting Ks/Vs/Ps
        // K tile [64 d x 32 m]
        #pragma unroll
        for (int e = tid; e < 64 * 32; e += 256) {
            int dd = e >> 5, mm = e & 31;
            Ks[dd][mm] = kb[dd * N_ + k0 + mm];
        }
        // V tile [32 m x 64 d]
        #pragma unroll
        for (int e = tid; e < 32 * 64; e += 256) {
            int dd = e >> 5, mm = e & 31;       // read coalesced over m
            Vs[mm][dd] = vb[dd * N_ + k0 + mm];
        }
        __syncthreads();

        // S = Q K^T (tile 64x32)
        float s[4][2];
        s[0][0]=0.f; s[0][1]=0.f; s[1][0]=0.f; s[1][1]=0.f;
        s[2][0]=0.f; s[2][1]=0.f; s[3][0]=0.f; s[3][1]=0.f;
        #pragma unroll 16
        for (int dd = 0; dd < 64; ++dd) {
            float qv0 = Qs[4 * ty + 0][dd];
            float qv1 = Qs[4 * ty + 1][dd];
            float qv2 = Qs[4 * ty + 2][dd];
            float qv3 = Qs[4 * ty + 3][dd];
            float kk0 = Ks[dd][2 * tx + 0];
            float kk1 = Ks[dd][2 * tx + 1];
            s[0][0] += qv0 * kk0; s[0][1] += qv0 * kk1;
            s[1][0] += qv1 * kk0; s[1][1] += qv1 * kk1;
            s[2][0] += qv2 * kk0; s[2][1] += qv2 * kk1;
            s[3][0] += qv3 * kk0; s[3][1] += qv3 * kk1;
        }

        // scale + drop mask
        #pragma unroll
        for (int i = 0; i < 4; i++) {
            int midx = mrow0 + (4 * ty + i) * N_ + k0 + 2 * tx;
            #pragma unroll
            for (int j = 0; j < 2; j++) {
                float sv = s[i][j] * scale;
                bool mk;
                if (mode == 0)      mk = mask_raw[midx + j] != 0;
                else if (mode == 1) mk = mask_i32[midx + j] != 0;
                else                mk = mask_f32[midx + j] != 0.f;
                s[i][j] = mk ? -FLT_MAX : sv;
            }
        }

        // Online softmax (row reductions across 16-lane half-warp groups)
        #pragma unroll
        for (int i = 0; i < 4; i++) {
            float mt = fmaxf(s[i][0], s[i][1]);
            #pragma unroll
            for (int o = 8; o >= 1; o >>= 1)
                mt = fmaxf(mt, __shfl_xor_sync(0xffffffffu, mt, o, 16));
            float mnew = fmaxf(m_i[i], mt);
            float corr = __expf(m_i[i] - mnew);
            float p0 = __expf(s[i][0] - mnew);
            float p1 = __expf(s[i][1] - mnew);
            Ps[4 * ty + i][2 * tx + 0] = p0;
            Ps[4 * ty + i][2 * tx + 1] = p1;
            float ls = p0 + p1;
            #pragma unroll
            for (int o = 8; o >= 1; o >>= 1)
                ls += __shfl_xor_sync(0xffffffffu, ls, o, 16);
            l_i[i] = l_i[i] * corr + ls;
            m_i[i] = mnew;
            o_acc[i][0] *= corr; o_acc[i][1] *= corr;
            o_acc[i][2] *= corr; o_acc[i][3] *= corr;
        }
        __syncthreads();   // Ps fully written before PV reads it

        // O += P V
        #pragma unroll 8
        for (int mm = 0; mm < 32; ++mm) {
            float p0 = Ps[4 * ty + 0][mm];
            float p1 = Ps[4 * ty + 1][mm];
            float p2 = Ps[4 * ty + 2][mm];
            float p3 = Ps[4 * ty + 3][mm];
            float v0 = Vs[mm][4 * tx + 0];
            float v1 = Vs[mm][4 * tx + 1];
            float v2 = Vs[mm][4 * tx + 2];
            float v3 = Vs[mm][4 * tx + 3];
            o_acc[0][0] += p0 * v0; o_acc[0][1] += p0 * v1; o_acc[0][2] += p0 * v2; o_acc[0][3] += p0 * v3;
            o_acc[1][0] += p1 * v0; o_acc[1][1] += p1 * v1; o_acc[1][2] += p1 * v2; o_acc[1][3] += p1 * v3;
            o_acc[2][0] += p2 * v0; o_acc[2][1] += p2 * v1; o_acc[2][2] += p2 * v2; o_acc[2][3] += p2 * v3;
            o_acc[3][0] += p3 * v0; o_acc[3][1] += p3 * v1; o_acc[3][2] += p3 * v2; o_acc[3][3] += p3 * v3;
        }
    }

    // Write out[b][h*64 + d][n] = O[n_row][d] / l
    float* ob = out + (b * C_ + h * D_) * N_;
    #pragma unroll
    for (int i = 0; i < 4; i++) {
        float inv_l = 1.0f / l_i[i];
        #pragma unroll
        for (int j = 0; j < 4; j++)
            ob[(4 * tx + j) * N_ + q0 + 4 * ty + i] = o_acc[i][j] * inv_l;
    }
}

// ---------------------------------------------------------------------------
extern "C" void kernel_launch(void* const* d_in, const int* in_sizes, int n_in,
                              void* d_out, int out_size)
{
    const float* x         = (const float*)d_in[0];   // (16, 384, 32, 32)
    const float* w_qkv     = (const float*)d_in[1];   // (1152, 384)
    const unsigned char* m = (const unsigned char*)d_in[2]; // (16,6,1024,1024) bool
    float* out             = (float*)d_out;           // (16, 384, 32, 32)

    detect_mask_kernel<<<1, 256>>>(m);

    dim3 gemm_grid(N_ / 64, O3C / 64, B_);   // (16, 18, 16)
    qkv_gemm_kernel<<<gemm_grid, dim3(16, 16)>>>(x, w_qkv);

    dim3 attn_grid(N_ / 64, HEADS_, B_);     // (16, 6, 16)
    attn_kernel<<<attn_grid, dim3(16, 16)>>>(m, out);
}

// round 2
// speedup vs baseline: 1.1754x; 1.1754x over previous
#include <cuda_runtime.h>
#include <math.h>
#include <float.h>

// Problem constants
#define B_     16
#define C_     384
#define HEADS_ 6
#define D_     64          // C_/HEADS_
#define N_     1024        // H*W = 32*32
#define O3C    1152        // 3*C_

// Scratch: qkv[b][o][n], o in [0,3C): rows [0,C)=Q, [C,2C)=K, [2C,3C)=V
__device__ float g_qkv[B_ * O3C * N_];
__device__ int g_mask_mode;   // 0 = uint8 bool, 1 = int32, 2 = float32

// ---------------------------------------------------------------------------
// Fast exp2: FMA-only (no MUFU). |rel err| ~2e-6 on f in [-0.5, 0.5].
// Input y: exponent in base 2, y <= ~0 (clamped at -126 -> result ~0).
// ---------------------------------------------------------------------------
__device__ __forceinline__ float fexp2(float y) {
    y = fmaxf(y, -126.0f);
    float z = y + 12582912.0f;                 // 1.5*2^23: round-to-nearest int
    int   n = __float_as_int(z) - 0x4B400000;  // n = rint(y) as integer
    float f = y - (z - 12582912.0f);           // f in [-0.5, 0.5]
    float p = 1.3333558146e-3f;                // Taylor: ln2^k/k!
    p = fmaf(p, f, 9.6181291076e-3f);
    p = fmaf(p, f, 5.5504108665e-2f);
    p = fmaf(p, f, 2.4022650696e-1f);
    p = fmaf(p, f, 6.9314718056e-1f);
    p = fmaf(p, f, 1.0f);
    return __int_as_float(__float_as_int(p) + (n << 23));
}

// ---------------------------------------------------------------------------
// Mask dtype detection (vectorized).
// u8 bool  : bytes in {0,1}, ones at arbitrary byte offsets
// int32 0/1: nonzero bytes ONLY at offset % 4 == 0
// float32  : contains bytes > 1 (1.0f = 00 00 80 3F)
// ---------------------------------------------------------------------------
__global__ void detect_mask_kernel(const uint4* __restrict__ m) {
    __shared__ int s_off4, s_gt1;
    if (threadIdx.x == 0) { s_off4 = 0; s_gt1 = 0; }
    __syncthreads();
    int off4 = 0, gt1 = 0;
    for (int i = threadIdx.x; i < 4096; i += blockDim.x) {   // 64 KB sample
        uint4 v = m[i];
        unsigned a = v.x | v.y | v.z | v.w;
        if (a & 0xFFFFFF00u) off4 = 1;   // nonzero byte at offset%4 != 0
        if (a & 0xFEFEFEFEu) gt1  = 1;   // some byte > 1
    }
    if (off4) atomicOr(&s_off4, 1);
    if (gt1)  atomicOr(&s_gt1, 1);
    __syncthreads();
    if (threadIdx.x == 0) g_mask_mode = s_gt1 ? 2 : (s_off4 ? 0 : 1);
}

// ---------------------------------------------------------------------------
// QKV GEMM: qkv[b][o][n] = sum_c w[o][c] * x[b][c][n]
// 128(o) x 128(n) tile, BK=16, 256 threads, 8x8 micro-tile, float4 everywhere.
// grid = (N/128, 3C/128, B) = (8, 9, 16)
// ---------------------------------------------------------------------------
#define GBM 128
#define GBN 128
#define GBK 16
#define GPAD 4

__global__ __launch_bounds__(256) void qkv_gemm_kernel(
    const float* __restrict__ x, const float* __restrict__ w)
{
    __shared__ float Ws[GBK][GBM + GPAD];   // [c_local][o_local]
    __shared__ float Xs[GBK][GBN + GPAD];   // [c_local][n_local]

    const int b  = blockIdx.z;
    const int o0 = blockIdx.y * GBM;
    const int n0 = blockIdx.x * GBN;
    const int tx = threadIdx.x & 15;        // 0..15 -> n micro
    const int ty = threadIdx.x >> 4;        // 0..15 -> o micro
    const int tid = threadIdx.x;

    const float* xb = x + b * C_ * N_;

    // loader indices
    const int wo = tid >> 1;                // 0..127 (o row)
    const int wc = (tid & 1) * 8;           // 0 or 8 (c col)
    const int xc = tid >> 4;                // 0..15 (c row)
    const int xn = (tid & 15) * 8;          // n col

    float acc[8][8];
    #pragma unroll
    for (int i = 0; i < 8; i++)
        #pragma unroll
        for (int j = 0; j < 8; j++) acc[i][j] = 0.f;

    for (int c0 = 0; c0 < C_; c0 += GBK) {
        // W tile 128(o) x 16(c), transposed into Ws[c][o]
        float4 wv0 = *(const float4*)&w[(o0 + wo) * C_ + c0 + wc];
        float4 wv1 = *(const float4*)&w[(o0 + wo) * C_ + c0 + wc + 4];
        Ws[wc + 0][wo] = wv0.x; Ws[wc + 1][wo] = wv0.y;
        Ws[wc + 2][wo] = wv0.z; Ws[wc + 3][wo] = wv0.w;
        Ws[wc + 4][wo] = wv1.x; Ws[wc + 5][wo] = wv1.y;
        Ws[wc + 6][wo] = wv1.z; Ws[wc + 7][wo] = wv1.w;
        // X tile 16(c) x 128(n)
        *(float4*)&Xs[xc][xn]     = *(const float4*)&xb[(c0 + xc) * N_ + n0 + xn];
        *(float4*)&Xs[xc][xn + 4] = *(const float4*)&xb[(c0 + xc) * N_ + n0 + xn + 4];
        __syncthreads();

        #pragma unroll
        for (int kk = 0; kk < GBK; ++kk) {
            float4 a0 = *(const float4*)&Ws[kk][ty * 8];
            float4 a1 = *(const float4*)&Ws[kk][ty * 8 + 4];
            float4 b0 = *(const float4*)&Xs[kk][tx * 8];
            float4 b1 = *(const float4*)&Xs[kk][tx * 8 + 4];
            float av[8] = {a0.x, a0.y, a0.z, a0.w, a1.x, a1.y, a1.z, a1.w};
            float bv[8] = {b0.x, b0.y, b0.z, b0.w, b1.x, b1.y, b1.z, b1.w};
            #pragma unroll
            for (int i = 0; i < 8; i++)
                #pragma unroll
                for (int j = 0; j < 8; j++)
                    acc[i][j] = fmaf(av[i], bv[j], acc[i][j]);
        }
        __syncthreads();
    }

    float* outb = g_qkv + b * O3C * N_;
    #pragma unroll
    for (int i = 0; i < 8; i++) {
        float* orow = &outb[(o0 + ty * 8 + i) * N_ + n0 + tx * 8];
        *(float4*)orow       = make_float4(acc[i][0], acc[i][1], acc[i][2], acc[i][3]);
        *(float4*)(orow + 4) = make_float4(acc[i][4], acc[i][5], acc[i][6], acc[i][7]);
    }
}

// ---------------------------------------------------------------------------
// Fused attention: per (b, h, 64-query tile). Online-softmax, FMA-only exp.
// 256 threads (16x16). TQ=64, TK=32, D=64.
// grid = (16, 6, 16) = (qtile, head, batch)
// ---------------------------------------------------------------------------
__global__ __launch_bounds__(256) void attn_kernel(
    const unsigned char* __restrict__ mask_raw, float* __restrict__ out)
{
    __shared__ float Qs[64][65];   // [q_row][d]
    __shared__ float Ks[64][34];   // [d][k_col]   (34 keeps float2 8B-aligned)
    __shared__ float Vs[32][68];   // [k_col][d]   (68 keeps float4 16B-aligned)
    __shared__ float Ps[64][33];   // [q_row][k_col]

    const int q0 = blockIdx.x * 64;
    const int h  = blockIdx.y;
    const int b  = blockIdx.z;
    const int tx = threadIdx.x, ty = threadIdx.y;
    const int tid = ty * 16 + tx;
    const int mode = g_mask_mode;

    // combined scale: score * C^-0.5 * log2(e)  (softmax done in base 2)
    const float sc2 = rsqrtf((float)C_) * 1.4426950408889634f;
    const float NEG = -1e30f;

    const float* qb = g_qkv + (b * O3C + h * D_) * N_;
    const float* kb = qb + C_ * N_;
    const float* vb = qb + 2 * C_ * N_;

    const int* mask_i32   = (const int*)mask_raw;
    const float* mask_f32 = (const float*)mask_raw;
    const int mrow0 = ((b * HEADS_ + h) * N_ + q0) * N_;

    // Load Q tile [64 rows x 64 d]
    #pragma unroll
    for (int e = tid; e < 64 * 64; e += 256) {
        int dd = e >> 6, r = e & 63;
        Qs[r][dd] = qb[dd * N_ + q0 + r];
    }

    float o_acc[4][4];
    float m_i[4], l_i[4];
    #pragma unroll
    for (int i = 0; i < 4; i++) {
        m_i[i] = NEG;
        l_i[i] = 0.f;
        #pragma unroll
        for (int j = 0; j < 4; j++) o_acc[i][j] = 0.f;
    }

    for (int k0 = 0; k0 < N_; k0 += 32) {
        __syncthreads();
        // K tile [64 d x 32 m]
        #pragma unroll
        for (int e = tid; e < 64 * 32; e += 256) {
            int dd = e >> 5, mm = e & 31;
            Ks[dd][mm] = kb[dd * N_ + k0 + mm];
        }
        // V tile [32 m x 64 d]
        #pragma unroll
        for (int e = tid; e < 32 * 64; e += 256) {
            int dd = e >> 5, mm = e & 31;
            Vs[mm][dd] = vb[dd * N_ + k0 + mm];
        }
        __syncthreads();

        // S = Q K^T (tile 64x32), micro 4x2
        float s[4][2];
        s[0][0]=0.f; s[0][1]=0.f; s[1][0]=0.f; s[1][1]=0.f;
        s[2][0]=0.f; s[2][1]=0.f; s[3][0]=0.f; s[3][1]=0.f;
        #pragma unroll 16
        for (int dd = 0; dd < 64; ++dd) {
            float qv0 = Qs[4 * ty + 0][dd];
            float qv1 = Qs[4 * ty + 1][dd];
            float qv2 = Qs[4 * ty + 2][dd];
            float qv3 = Qs[4 * ty + 3][dd];
            float2 kk = *(const float2*)&Ks[dd][2 * tx];
            s[0][0] = fmaf(qv0, kk.x, s[0][0]); s[0][1] = fmaf(qv0, kk.y, s[0][1]);
            s[1][0] = fmaf(qv1, kk.x, s[1][0]); s[1][1] = fmaf(qv1, kk.y, s[1][1]);
            s[2][0] = fmaf(qv2, kk.x, s[2][0]); s[2][1] = fmaf(qv2, kk.y, s[2][1]);
            s[3][0] = fmaf(qv3, kk.x, s[3][0]); s[3][1] = fmaf(qv3, kk.y, s[3][1]);
        }

        // scale to base-2 + drop mask
        #pragma unroll
        for (int i = 0; i < 4; i++) {
            int midx = mrow0 + (4 * ty + i) * N_ + k0 + 2 * tx;
            #pragma unroll
            for (int j = 0; j < 2; j++) {
                float sv = s[i][j] * sc2;
                bool mk;
                if (mode == 0)      mk = mask_raw[midx + j] != 0;
                else if (mode == 1) mk = mask_i32[midx + j] != 0;
                else                mk = mask_f32[midx + j] != 0.f;
                s[i][j] = mk ? NEG : sv;
            }
        }

        // Online softmax in base-2 (16-lane half-warp row groups)
        #pragma unroll
        for (int i = 0; i < 4; i++) {
            float mt = fmaxf(s[i][0], s[i][1]);
            #pragma unroll
            for (int o = 8; o >= 1; o >>= 1)
                mt = fmaxf(mt, __shfl_xor_sync(0xffffffffu, mt, o, 16));
            float mnew = fmaxf(m_i[i], mt);
            float corr = fexp2(m_i[i] - mnew);
            float p0 = fexp2(s[i][0] - mnew);
            float p1 = fexp2(s[i][1] - mnew);
            Ps[4 * ty + i][2 * tx + 0] = p0;
            Ps[4 * ty + i][2 * tx + 1] = p1;
            float ls = p0 + p1;
            #pragma unroll
            for (int o = 8; o >= 1; o >>= 1)
                ls += __shfl_xor_sync(0xffffffffu, ls, o, 16);
            l_i[i] = l_i[i] * corr + ls;
            m_i[i] = mnew;
            o_acc[i][0] *= corr; o_acc[i][1] *= corr;
            o_acc[i][2] *= corr; o_acc[i][3] *= corr;
        }
        __syncthreads();

        // O += P V  (micro 4x4), V as float4
        #pragma unroll 8
        for (int mm = 0; mm < 32; ++mm) {
            float p0 = Ps[4 * ty + 0][mm];
            float p1 = Ps[4 * ty + 1][mm];
            float p2 = Ps[4 * ty + 2][mm];
            float p3 = Ps[4 * ty + 3][mm];
            float4 v = *(const float4*)&Vs[mm][4 * tx];
            o_acc[0][0] = fmaf(p0, v.x, o_acc[0][0]); o_acc[0][1] = fmaf(p0, v.y, o_acc[0][1]);
            o_acc[0][2] = fmaf(p0, v.z, o_acc[0][2]); o_acc[0][3] = fmaf(p0, v.w, o_acc[0][3]);
            o_acc[1][0] = fmaf(p1, v.x, o_acc[1][0]); o_acc[1][1] = fmaf(p1, v.y, o_acc[1][1]);
            o_acc[1][2] = fmaf(p1, v.z, o_acc[1][2]); o_acc[1][3] = fmaf(p1, v.w, o_acc[1][3]);
            o_acc[2][0] = fmaf(p2, v.x, o_acc[2][0]); o_acc[2][1] = fmaf(p2, v.y, o_acc[2][1]);
            o_acc[2][2] = fmaf(p2, v.z, o_acc[2][2]); o_acc[2][3] = fmaf(p2, v.w, o_acc[2][3]);
            o_acc[3][0] = fmaf(p3, v.x, o_acc[3][0]); o_acc[3][1] = fmaf(p3, v.y, o_acc[3][1]);
            o_acc[3][2] = fmaf(p3, v.z, o_acc[3][2]); o_acc[3][3] = fmaf(p3, v.w, o_acc[3][3]);
        }
    }

    // out[b][h*64 + d][n]: columns q0+4ty+i are contiguous -> float4 stores
    float* ob = out + (b * C_ + h * D_) * N_;
    float inv_l[4];
    #pragma unroll
    for (int i = 0; i < 4; i++) inv_l[i] = 1.0f / l_i[i];
    #pragma unroll
    for (int j = 0; j < 4; j++) {
        float4 vv = make_float4(o_acc[0][j] * inv_l[0], o_acc[1][j] * inv_l[1],
                                o_acc[2][j] * inv_l[2], o_acc[3][j] * inv_l[3]);
        *(float4*)&ob[(4 * tx + j) * N_ + q0 + 4 * ty] = vv;
    }
}

// ---------------------------------------------------------------------------
extern "C" void kernel_launch(void* const* d_in, const int* in_sizes, int n_in,
                              void* d_out, int out_size)
{
    const float* x         = (const float*)d_in[0];   // (16, 384, 32, 32)
    const float* w_qkv     = (const float*)d_in[1];   // (1152, 384)
    const unsigned char* m = (const unsigned char*)d_in[2]; // (16,6,1024,1024)
    float* out             = (float*)d_out;           // (16, 384, 32, 32)

    detect_mask_kernel<<<1, 1024>>>((const uint4*)m);

    dim3 gemm_grid(N_ / GBN, O3C / GBM, B_);   // (8, 9, 16)
    qkv_gemm_kernel<<<gemm_grid, 256>>>(x, w_qkv);

    dim3 attn_grid(N_ / 64, HEADS_, B_);       // (16, 6, 16)
    attn_kernel<<<attn_grid, dim3(16, 16)>>>(m, out);
}

// round 3
// speedup vs baseline: 2.4436x; 2.0789x over previous
#include <cuda_runtime.h>
#include <math.h>
#include <float.h>
#include <stdint.h>

// Problem constants
#define B_     16
#define C_     384
#define HEADS_ 6
#define D_     64
#define N_     1024
#define O3C    1152

__device__ float g_qkv[B_ * O3C * N_];
__device__ int g_mask_mode;   // 0 = uint8 bool, 1 = int32, 2 = float32

// ---------------------------------------------------------------------------
__device__ __forceinline__ uint32_t f2tf32(float f) {
    uint32_t r;
    asm("cvt.rna.tf32.f32 %0, %1;" : "=r"(r) : "f"(f));
    return r;
}

// m16n8k8 tf32 mma, row.col, f32 accumulate (in-place C)
__device__ __forceinline__ void mma8(float* c, const uint32_t* a,
                                     uint32_t b0, uint32_t b1) {
    asm volatile(
        "mma.sync.aligned.m16n8k8.row.col.f32.tf32.tf32.f32 "
        "{%0,%1,%2,%3}, {%4,%5,%6,%7}, {%8,%9}, {%0,%1,%2,%3};\n"
        : "+f"(c[0]), "+f"(c[1]), "+f"(c[2]), "+f"(c[3])
        : "r"(a[0]), "r"(a[1]), "r"(a[2]), "r"(a[3]), "r"(b0), "r"(b1));
}

// Fast exp2, FMA-only
__device__ __forceinline__ float fexp2(float y) {
    y = fmaxf(y, -126.0f);
    float z = y + 12582912.0f;
    int   n = __float_as_int(z) - 0x4B400000;
    float f = y - (z - 12582912.0f);
    float p = 1.3333558146e-3f;
    p = fmaf(p, f, 9.6181291076e-3f);
    p = fmaf(p, f, 5.5504108665e-2f);
    p = fmaf(p, f, 2.4022650696e-1f);
    p = fmaf(p, f, 6.9314718056e-1f);
    p = fmaf(p, f, 1.0f);
    return __int_as_float(__float_as_int(p) + (n << 23));
}

// ---------------------------------------------------------------------------
__global__ void detect_mask_kernel(const uint4* __restrict__ m) {
    __shared__ int s_off4, s_gt1;
    if (threadIdx.x == 0) { s_off4 = 0; s_gt1 = 0; }
    __syncthreads();
    int off4 = 0, gt1 = 0;
    for (int i = threadIdx.x; i < 4096; i += blockDim.x) {
        uint4 v = m[i];
        unsigned a = v.x | v.y | v.z | v.w;
        if (a & 0xFFFFFF00u) off4 = 1;
        if (a & 0xFEFEFEFEu) gt1  = 1;
    }
    if (off4) atomicOr(&s_off4, 1);
    if (gt1)  atomicOr(&s_gt1, 1);
    __syncthreads();
    if (threadIdx.x == 0) g_mask_mode = s_gt1 ? 2 : (s_off4 ? 0 : 1);
}

// ---------------------------------------------------------------------------
// QKV GEMM, split tf32 (hi/lo): qkv[b][o][n] = sum_c w[o][c] * x[b][c][n]
// Tile 128(o) x 128(n), KC=16. 8 warps, warp tile 32(o) x 64(n).
// grid = (8, 9, 16)
// ---------------------------------------------------------------------------
#define WST 20     // Wh row stride (16 + 4): conflict-free A frags
#define XST 132    // Xh row stride (128 + 4)

__global__ __launch_bounds__(256, 2) void qkv_gemm_kernel(
    const float* __restrict__ x, const float* __restrict__ w)
{
    __shared__ uint32_t Wh[128 * WST], Wl[128 * WST];
    __shared__ uint32_t Xh[16 * XST],  Xl[16 * XST];

    const int b  = blockIdx.z;
    const int o0 = blockIdx.y * 128;
    const int n0 = blockIdx.x * 128;
    const int tid  = threadIdx.x;
    const int wid  = tid >> 5;
    const int lane = tid & 31;
    const int m_base = (wid >> 1) * 32;
    const int n_base = (wid & 1) * 64;
    const int gi = lane >> 2;     // group id
    const int ti = lane & 3;      // thread in group

    const float* xb = x + b * C_ * N_;

    // loader indices
    const int wo = tid >> 1;             // 0..127
    const int wc = (tid & 1) * 8;        // 0 or 8
    const int xc = tid >> 4;             // 0..15
    const int xn = (tid & 15) * 8;

    float acc[2][8][4];
    #pragma unroll
    for (int mf = 0; mf < 2; mf++)
        #pragma unroll
        for (int nf = 0; nf < 8; nf++)
            #pragma unroll
            for (int k = 0; k < 4; k++) acc[mf][nf][k] = 0.f;

    for (int c0 = 0; c0 < C_; c0 += 16) {
        // W tile 128 x 16 -> hi/lo
        {
            const float* wp = &w[(o0 + wo) * C_ + c0 + wc];
            float4 v0 = *(const float4*)wp;
            float4 v1 = *(const float4*)(wp + 4);
            float vv[8] = {v0.x, v0.y, v0.z, v0.w, v1.x, v1.y, v1.z, v1.w};
            uint32_t h[8], l[8];
            #pragma unroll
            for (int j = 0; j < 8; j++) {
                h[j] = f2tf32(vv[j]);
                l[j] = f2tf32(vv[j] - __uint_as_float(h[j]));
            }
            uint32_t* dh = &Wh[wo * WST + wc];
            uint32_t* dl = &Wl[wo * WST + wc];
            *(uint4*)dh       = make_uint4(h[0], h[1], h[2], h[3]);
            *(uint4*)(dh + 4) = make_uint4(h[4], h[5], h[6], h[7]);
            *(uint4*)dl       = make_uint4(l[0], l[1], l[2], l[3]);
            *(uint4*)(dl + 4) = make_uint4(l[4], l[5], l[6], l[7]);
        }
        // X tile 16 x 128 -> hi/lo
        {
            const float* xp = &xb[(c0 + xc) * N_ + n0 + xn];
            float4 v0 = *(const float4*)xp;
            float4 v1 = *(const float4*)(xp + 4);
            float vv[8] = {v0.x, v0.y, v0.z, v0.w, v1.x, v1.y, v1.z, v1.w};
            uint32_t h[8], l[8];
            #pragma unroll
            for (int j = 0; j < 8; j++) {
                h[j] = f2tf32(vv[j]);
                l[j] = f2tf32(vv[j] - __uint_as_float(h[j]));
            }
            uint32_t* dh = &Xh[xc * XST + xn];
            uint32_t* dl = &Xl[xc * XST + xn];
            *(uint4*)dh       = make_uint4(h[0], h[1], h[2], h[3]);
            *(uint4*)(dh + 4) = make_uint4(h[4], h[5], h[6], h[7]);
            *(uint4*)dl       = make_uint4(l[0], l[1], l[2], l[3]);
            *(uint4*)(dl + 4) = make_uint4(l[4], l[5], l[6], l[7]);
        }
        __syncthreads();

        #pragma unroll
        for (int ks = 0; ks < 2; ks++) {
            const int k = ks * 8;
            uint32_t ah[2][4], al[2][4];
            #pragma unroll
            for (int mf = 0; mf < 2; mf++) {
                int r = m_base + mf * 16 + gi;
                ah[mf][0] = Wh[r * WST + k + ti];
                ah[mf][1] = Wh[(r + 8) * WST + k + ti];
                ah[mf][2] = Wh[r * WST + k + ti + 4];
                ah[mf][3] = Wh[(r + 8) * WST + k + ti + 4];
                al[mf][0] = Wl[r * WST + k + ti];
                al[mf][1] = Wl[(r + 8) * WST + k + ti];
                al[mf][2] = Wl[r * WST + k + ti + 4];
                al[mf][3] = Wl[(r + 8) * WST + k + ti + 4];
            }
            #pragma unroll
            for (int nf = 0; nf < 8; nf++) {
                int col = n_base + nf * 8 + gi;
                uint32_t bh0 = Xh[(k + ti) * XST + col];
                uint32_t bh1 = Xh[(k + ti + 4) * XST + col];
                uint32_t bl0 = Xl[(k + ti) * XST + col];
                uint32_t bl1 = Xl[(k + ti + 4) * XST + col];
                #pragma unroll
                for (int mf = 0; mf < 2; mf++) {
                    mma8(acc[mf][nf], ah[mf], bh0, bh1);
                    mma8(acc[mf][nf], ah[mf], bl0, bl1);
                    mma8(acc[mf][nf], al[mf], bh0, bh1);
                }
            }
        }
        __syncthreads();
    }

    float* outb = g_qkv + b * O3C * N_;
    #pragma unroll
    for (int mf = 0; mf < 2; mf++) {
        int r = o0 + m_base + mf * 16 + gi;
        #pragma unroll
        for (int nf = 0; nf < 8; nf++) {
            int nc = n0 + n_base + nf * 8 + 2 * ti;
            *(float2*)&outb[r * N_ + nc]       = make_float2(acc[mf][nf][0], acc[mf][nf][1]);
            *(float2*)&outb[(r + 8) * N_ + nc] = make_float2(acc[mf][nf][2], acc[mf][nf][3]);
        }
    }
}

// ---------------------------------------------------------------------------
// Fused flash attention with tf32 mma. Block: 128 q rows, 8 warps (16 q each).
// TK chunk = 64. grid = (8, 6, 16).
// Dynamic smem: QP[128*68] (Q, then reused for P), Kt[64*68] (K^T as [m][d]),
// Vh[64*68] ([d][m]). Output staged in Kt/Vh space.
// ---------------------------------------------------------------------------
#define AST 68
#define ATTN_SMEM ((128 * AST + 64 * AST + 64 * AST) * 4)

__global__ __launch_bounds__(256, 2) void attn_kernel(
    const unsigned char* __restrict__ mask_raw, float* __restrict__ out)
{
    extern __shared__ uint32_t As[];
    uint32_t* QP = As;                       // [128][AST]
    uint32_t* Kt = As + 128 * AST;           // [64][AST]  K^T: [m][d]
    uint32_t* Vh = Kt + 64 * AST;            // [64][AST]  V: [d][m]
    float*    Od = (float*)Kt;               // [64][132] output staging (reuse)

    const int q0 = blockIdx.x * 128;
    const int h  = blockIdx.y;
    const int b  = blockIdx.z;
    const int tid  = threadIdx.x;
    const int wid  = tid >> 5;
    const int lane = tid & 31;
    const int gi = lane >> 2;
    const int ti = lane & 3;
    const int wq = wid * 16;
    const int mode = g_mask_mode;

    const float sc2 = rsqrtf((float)C_) * 1.4426950408889634f;
    const float NEG = -1e30f;

    const float* qb = g_qkv + (b * O3C + h * D_) * N_;
    const float* kb = qb + C_ * N_;
    const float* vb = qb + 2 * C_ * N_;

    const int* mask_i32   = (const int*)mask_raw;
    const float* mask_f32 = (const float*)mask_raw;
    const int mbase = (b * HEADS_ + h) * N_ * N_;

    // ---- Load Q tile [128 q x 64 d], transposed, tf32 ----
    for (int e = tid; e < 128 * 64; e += 256) {
        int dd = e >> 7, qq = e & 127;
        QP[qq * AST + dd] = f2tf32(qb[dd * N_ + q0 + qq]);
    }
    __syncthreads();

    // ---- Cache Q A-fragments in registers (whole kernel) ----
    uint32_t qa[8][4];
    #pragma unroll
    for (int ks = 0; ks < 8; ks++) {
        int r = wq + gi, c = ks * 8 + ti;
        qa[ks][0] = QP[r * AST + c];
        qa[ks][1] = QP[(r + 8) * AST + c];
        qa[ks][2] = QP[r * AST + c + 4];
        qa[ks][3] = QP[(r + 8) * AST + c + 4];
    }
    __syncthreads();   // all warps done reading Q before QP is reused as P

    float oa[8][4];
    #pragma unroll
    for (int nf = 0; nf < 8; nf++)
        #pragma unroll
        for (int k = 0; k < 4; k++) oa[nf][k] = 0.f;
    float m1 = NEG, m2 = NEG, l1 = 0.f, l2 = 0.f;

    const int r1g = q0 + wq + gi;        // global q row (c0,c1)

    for (int k0 = 0; k0 < N_; k0 += 64) {
        // ---- Fill K^T [m][d] (scalar transpose) and V [d][m] (vectorized) ----
        for (int e = tid; e < 4096; e += 256) {
            int dd = e >> 6, mm = e & 63;
            Kt[mm * AST + dd] = f2tf32(kb[dd * N_ + k0 + mm]);
        }
        for (int e = tid; e < 1024; e += 256) {
            int dd = e >> 4, m4 = (e & 15) * 4;
            float4 v = *(const float4*)&vb[dd * N_ + k0 + m4];
            *(uint4*)&Vh[dd * AST + m4] =
                make_uint4(f2tf32(v.x), f2tf32(v.y), f2tf32(v.z), f2tf32(v.w));
        }
        __syncthreads();

        // ---- S = Q K^T : warp computes [16 x 64] ----
        float sa[8][4];
        #pragma unroll
        for (int nf = 0; nf < 8; nf++)
            #pragma unroll
            for (int k = 0; k < 4; k++) sa[nf][k] = 0.f;
        #pragma unroll
        for (int ks = 0; ks < 8; ks++) {
            #pragma unroll
            for (int nf = 0; nf < 8; nf++) {
                uint32_t b0 = Kt[(nf * 8 + gi) * AST + ks * 8 + ti];
                uint32_t b1 = Kt[(nf * 8 + gi) * AST + ks * 8 + ti + 4];
                mma8(sa[nf], qa[ks], b0, b1);
            }
        }

        // ---- scale + mask ----
        #pragma unroll
        for (int nf = 0; nf < 8; nf++) {
            int cb = k0 + nf * 8 + 2 * ti;
            int i1 = mbase + r1g * N_ + cb;
            int i2 = i1 + 8 * N_;
            bool k00, k01, k10, k11;
            if (mode == 0) {
                uchar2 a = *(const uchar2*)&mask_raw[i1];
                uchar2 c = *(const uchar2*)&mask_raw[i2];
                k00 = a.x; k01 = a.y; k10 = c.x; k11 = c.y;
            } else if (mode == 1) {
                int2 a = *(const int2*)&mask_i32[i1];
                int2 c = *(const int2*)&mask_i32[i2];
                k00 = a.x; k01 = a.y; k10 = c.x; k11 = c.y;
            } else {
                float2 a = *(const float2*)&mask_f32[i1];
                float2 c = *(const float2*)&mask_f32[i2];
                k00 = a.x != 0.f; k01 = a.y != 0.f; k10 = c.x != 0.f; k11 = c.y != 0.f;
            }
            sa[nf][0] = k00 ? NEG : sa[nf][0] * sc2;
            sa[nf][1] = k01 ? NEG : sa[nf][1] * sc2;
            sa[nf][2] = k10 ? NEG : sa[nf][2] * sc2;
            sa[nf][3] = k11 ? NEG : sa[nf][3] * sc2;
        }

        // ---- online softmax (rows r1: c0,c1 / r2: c2,c3), quad reduction ----
        float mx1 = NEG, mx2 = NEG;
        #pragma unroll
        for (int nf = 0; nf < 8; nf++) {
            mx1 = fmaxf(mx1, fmaxf(sa[nf][0], sa[nf][1]));
            mx2 = fmaxf(mx2, fmaxf(sa[nf][2], sa[nf][3]));
        }
        mx1 = fmaxf(mx1, __shfl_xor_sync(0xffffffffu, mx1, 1));
        mx1 = fmaxf(mx1, __shfl_xor_sync(0xffffffffu, mx1, 2));
        mx2 = fmaxf(mx2, __shfl_xor_sync(0xffffffffu, mx2, 1));
        mx2 = fmaxf(mx2, __shfl_xor_sync(0xffffffffu, mx2, 2));
        float mn1 = fmaxf(m1, mx1), mn2 = fmaxf(m2, mx2);
        float corr1 = fexp2(m1 - mn1), corr2 = fexp2(m2 - mn2);

        float ls1 = 0.f, ls2 = 0.f;
        #pragma unroll
        for (int nf = 0; nf < 8; nf++) {
            float p00 = fexp2(sa[nf][0] - mn1);
            float p01 = fexp2(sa[nf][1] - mn1);
            float p10 = fexp2(sa[nf][2] - mn2);
            float p11 = fexp2(sa[nf][3] - mn2);
            ls1 += p00 + p01;
            ls2 += p10 + p11;
            int col = nf * 8 + 2 * ti;
            QP[(wq + gi) * AST + col]     = f2tf32(p00);
            QP[(wq + gi) * AST + col + 1] = f2tf32(p01);
            QP[(wq + gi + 8) * AST + col]     = f2tf32(p10);
            QP[(wq + gi + 8) * AST + col + 1] = f2tf32(p11);
        }
        ls1 += __shfl_xor_sync(0xffffffffu, ls1, 1);
        ls1 += __shfl_xor_sync(0xffffffffu, ls1, 2);
        ls2 += __shfl_xor_sync(0xffffffffu, ls2, 1);
        ls2 += __shfl_xor_sync(0xffffffffu, ls2, 2);
        l1 = l1 * corr1 + ls1;
        l2 = l2 * corr2 + ls2;
        m1 = mn1; m2 = mn2;
        #pragma unroll
        for (int nf = 0; nf < 8; nf++) {
            oa[nf][0] *= corr1; oa[nf][1] *= corr1;
            oa[nf][2] *= corr2; oa[nf][3] *= corr2;
        }
        __syncwarp();   // P is warp-local (rows wq..wq+16): only warp sync needed

        // ---- O += P V : A = P [16x64], B = V [64(m) x 64(d)] ----
        #pragma unroll
        for (int kf = 0; kf < 8; kf++) {
            uint32_t pa[4];
            int r = wq + gi, c = kf * 8 + ti;
            pa[0] = QP[r * AST + c];
            pa[1] = QP[(r + 8) * AST + c];
            pa[2] = QP[r * AST + c + 4];
            pa[3] = QP[(r + 8) * AST + c + 4];
            #pragma unroll
            for (int nf = 0; nf < 8; nf++) {
                uint32_t b0 = Vh[(nf * 8 + gi) * AST + kf * 8 + ti];
                uint32_t b1 = Vh[(nf * 8 + gi) * AST + kf * 8 + ti + 4];
                mma8(oa[nf], pa, b0, b1);
            }
        }
        __syncthreads();   // all warps done with Kt/Vh before next fill
    }

    // ---- normalize + stage to smem [d][q] for coalesced output ----
    float il1 = 1.0f / l1, il2 = 1.0f / l2;
    #pragma unroll
    for (int nf = 0; nf < 8; nf++) {
        int d0 = nf * 8 + 2 * ti;
        Od[d0 * 132 + wq + gi]           = oa[nf][0] * il1;
        Od[(d0 + 1) * 132 + wq + gi]     = oa[nf][1] * il1;
        Od[d0 * 132 + wq + gi + 8]       = oa[nf][2] * il2;
        Od[(d0 + 1) * 132 + wq + gi + 8] = oa[nf][3] * il2;
    }
    __syncthreads();

    float* ob = out + (b * C_ + h * D_) * N_;
    for (int e = tid; e < 64 * 32; e += 256) {
        int dd = e >> 5, q4 = (e & 31) * 4;
        *(float4*)&ob[dd * N_ + q0 + q4] = *(const float4*)&Od[dd * 132 + q4];
    }
}

// ---------------------------------------------------------------------------
extern "C" void kernel_launch(void* const* d_in, const int* in_sizes, int n_in,
                              void* d_out, int out_size)
{
    const float* x         = (const float*)d_in[0];
    const float* w_qkv     = (const float*)d_in[1];
    const unsigned char* m = (const unsigned char*)d_in[2];
    float* out             = (float*)d_out;

    // Idempotent, host-side attribute set (not a stream op; capture-safe)
    cudaFuncSetAttribute(attn_kernel,
                         cudaFuncAttributeMaxDynamicSharedMemorySize, ATTN_SMEM);

    detect_mask_kernel<<<1, 1024>>>((const uint4*)m);

    dim3 gemm_grid(N_ / 128, O3C / 128, B_);   // (8, 9, 16)
    qkv_gemm_kernel<<<gemm_grid, 256>>>(x, w_qkv);

    dim3 attn_grid(N_ / 128, HEADS_, B_);      // (8, 6, 16)
    attn_kernel<<<attn_grid, 256, ATTN_SMEM>>>(m, out);
}

// round 4
// speedup vs baseline: 3.4350x; 1.4057x over previous
#include <cuda_runtime.h>
#include <cuda_bf16.h>
#include <math.h>
#include <float.h>
#include <stdint.h>

// Problem constants
#define B_     16
#define C_     384
#define HEADS_ 6
#define D_     64
#define N_     1024
#define O3C    1152

__device__ float g_qkv[B_ * O3C * N_];
__device__ int g_mask_mode;   // 0 = uint8 bool, 1 = int32, 2 = float32

// ---------------------------------------------------------------------------
__device__ __forceinline__ uint32_t f2tf32(float f) {
    uint32_t r;
    asm("cvt.rna.tf32.f32 %0, %1;" : "=r"(r) : "f"(f));
    return r;
}

// tf32 m16n8k8 row.col mma, f32 acc in-place
__device__ __forceinline__ void mma8(float* c, const uint32_t* a,
                                     uint32_t b0, uint32_t b1) {
    asm volatile(
        "mma.sync.aligned.m16n8k8.row.col.f32.tf32.tf32.f32 "
        "{%0,%1,%2,%3}, {%4,%5,%6,%7}, {%8,%9}, {%0,%1,%2,%3};\n"
        : "+f"(c[0]), "+f"(c[1]), "+f"(c[2]), "+f"(c[3])
        : "r"(a[0]), "r"(a[1]), "r"(a[2]), "r"(a[3]), "r"(b0), "r"(b1));
}

// bf16 m16n8k16 row.col mma, f32 acc in-place
__device__ __forceinline__ void mma16(float* c, const uint32_t* a,
                                      uint32_t b0, uint32_t b1) {
    asm volatile(
        "mma.sync.aligned.m16n8k16.row.col.f32.bf16.bf16.f32 "
        "{%0,%1,%2,%3}, {%4,%5,%6,%7}, {%8,%9}, {%0,%1,%2,%3};\n"
        : "+f"(c[0]), "+f"(c[1]), "+f"(c[2]), "+f"(c[3])
        : "r"(a[0]), "r"(a[1]), "r"(a[2]), "r"(a[3]), "r"(b0), "r"(b1));
}

// pack two floats -> bf16x2 (lo = first k element)
__device__ __forceinline__ uint32_t pack_bf16(float f0, float f1) {
    __nv_bfloat162 t = __floats2bfloat162_rn(f0, f1);
    return *(uint32_t*)&t;
}

// Fast exp2, FMA-only
__device__ __forceinline__ float fexp2(float y) {
    y = fmaxf(y, -126.0f);
    float z = y + 12582912.0f;
    int   n = __float_as_int(z) - 0x4B400000;
    float f = y - (z - 12582912.0f);
    float p = 1.3333558146e-3f;
    p = fmaf(p, f, 9.6181291076e-3f);
    p = fmaf(p, f, 5.5504108665e-2f);
    p = fmaf(p, f, 2.4022650696e-1f);
    p = fmaf(p, f, 6.9314718056e-1f);
    p = fmaf(p, f, 1.0f);
    return __int_as_float(__float_as_int(p) + (n << 23));
}

// ---------------------------------------------------------------------------
__global__ void detect_mask_kernel(const uint4* __restrict__ m) {
    __shared__ int s_off4, s_gt1;
    if (threadIdx.x == 0) { s_off4 = 0; s_gt1 = 0; }
    __syncthreads();
    int off4 = 0, gt1 = 0;
    for (int i = threadIdx.x; i < 4096; i += blockDim.x) {
        uint4 v = m[i];
        unsigned a = v.x | v.y | v.z | v.w;
        if (a & 0xFFFFFF00u) off4 = 1;
        if (a & 0xFEFEFEFEu) gt1  = 1;
    }
    if (off4) atomicOr(&s_off4, 1);
    if (gt1)  atomicOr(&s_gt1, 1);
    __syncthreads();
    if (threadIdx.x == 0) g_mask_mode = s_gt1 ? 2 : (s_off4 ? 0 : 1);
}

// ---------------------------------------------------------------------------
// QKV GEMM, bf16 hi/lo 3-term, m16n8k16.
// Tile 128(o) x 128(n), KC=16. 8 warps, warp tile 32(o) x 64(n).
// grid = (8, 9, 16)
// Whp: A packed [o][k2] (k-pairs), stride 12 words  -> A-frag banks 12g+t unique
// Xhp: B packed [c2][n] (vertical k-pairs), stride 136 -> B-frag banks 8t+g unique
// ---------------------------------------------------------------------------
#define WPST 12
#define XPST 136

__global__ __launch_bounds__(256, 2) void qkv_gemm_kernel(
    const float* __restrict__ x, const float* __restrict__ w)
{
    __shared__ uint32_t Whp[128 * WPST], Wlp[128 * WPST];
    __shared__ uint32_t Xhp[8 * XPST],   Xlp[8 * XPST];

    const int b  = blockIdx.z;
    const int o0 = blockIdx.y * 128;
    const int n0 = blockIdx.x * 128;
    const int tid  = threadIdx.x;
    const int wid  = tid >> 5;
    const int lane = tid & 31;
    const int m_base = (wid >> 1) * 32;
    const int n_base = (wid & 1) * 64;
    const int gi = lane >> 2;
    const int ti = lane & 3;

    const float* xb = x + b * C_ * N_;

    // loader indices
    const int wo  = tid >> 1;            // 0..127 (o row)
    const int wk  = (tid & 1) * 8;       // c offset 0/8
    const int xc2 = tid >> 5;            // 0..7 (c-pair row)
    const int xn  = (tid & 31) * 4;      // n col

    float acc[2][8][4];
    #pragma unroll
    for (int mf = 0; mf < 2; mf++)
        #pragma unroll
        for (int nf = 0; nf < 8; nf++)
            #pragma unroll
            for (int k = 0; k < 4; k++) acc[mf][nf][k] = 0.f;

    for (int c0 = 0; c0 < C_; c0 += 16) {
        // ---- W tile 128(o) x 16(c) -> bf16 hi/lo, k-pair packed ----
        {
            const float* wp = &w[(o0 + wo) * C_ + c0 + wk];
            float4 v0 = *(const float4*)wp;
            float4 v1 = *(const float4*)(wp + 4);
            float vv[8] = {v0.x, v0.y, v0.z, v0.w, v1.x, v1.y, v1.z, v1.w};
            uint32_t ph[4], pl[4];
            #pragma unroll
            for (int j = 0; j < 4; j++) {
                __nv_bfloat16 h0 = __float2bfloat16(vv[2*j]);
                __nv_bfloat16 h1 = __float2bfloat16(vv[2*j+1]);
                ph[j] = ((uint32_t)*(uint16_t*)&h1 << 16) | *(uint16_t*)&h0;
                pl[j] = pack_bf16(vv[2*j]   - __bfloat162float(h0),
                                  vv[2*j+1] - __bfloat162float(h1));
            }
            *(uint4*)&Whp[wo * WPST + wk / 2] = make_uint4(ph[0], ph[1], ph[2], ph[3]);
            *(uint4*)&Wlp[wo * WPST + wk / 2] = make_uint4(pl[0], pl[1], pl[2], pl[3]);
        }
        // ---- X tile 16(c) x 128(n) -> vertical k-pair packed ----
        {
            const float* xp0 = &xb[(c0 + 2 * xc2) * N_ + n0 + xn];
            float4 r0 = *(const float4*)xp0;
            float4 r1 = *(const float4*)(xp0 + N_);
            float a0[4] = {r0.x, r0.y, r0.z, r0.w};
            float a1[4] = {r1.x, r1.y, r1.z, r1.w};
            uint32_t ph[4], pl[4];
            #pragma unroll
            for (int j = 0; j < 4; j++) {
                __nv_bfloat16 h0 = __float2bfloat16(a0[j]);
                __nv_bfloat16 h1 = __float2bfloat16(a1[j]);
                ph[j] = ((uint32_t)*(uint16_t*)&h1 << 16) | *(uint16_t*)&h0;
                pl[j] = pack_bf16(a0[j] - __bfloat162float(h0),
                                  a1[j] - __bfloat162float(h1));
            }
            *(uint4*)&Xhp[xc2 * XPST + xn] = make_uint4(ph[0], ph[1], ph[2], ph[3]);
            *(uint4*)&Xlp[xc2 * XPST + xn] = make_uint4(pl[0], pl[1], pl[2], pl[3]);
        }
        __syncthreads();

        // ---- A fragments (k=16 covered by one frag set) ----
        uint32_t ah[2][4], al[2][4];
        #pragma unroll
        for (int mf = 0; mf < 2; mf++) {
            int r = m_base + mf * 16 + gi;
            ah[mf][0] = Whp[r * WPST + ti];
            ah[mf][1] = Whp[(r + 8) * WPST + ti];
            ah[mf][2] = Whp[r * WPST + ti + 4];
            ah[mf][3] = Whp[(r + 8) * WPST + ti + 4];
            al[mf][0] = Wlp[r * WPST + ti];
            al[mf][1] = Wlp[(r + 8) * WPST + ti];
            al[mf][2] = Wlp[r * WPST + ti + 4];
            al[mf][3] = Wlp[(r + 8) * WPST + ti + 4];
        }
        #pragma unroll
        for (int nf = 0; nf < 8; nf++) {
            int col = n_base + nf * 8 + gi;
            uint32_t bh0 = Xhp[ti * XPST + col];
            uint32_t bh1 = Xhp[(ti + 4) * XPST + col];
            uint32_t bl0 = Xlp[ti * XPST + col];
            uint32_t bl1 = Xlp[(ti + 4) * XPST + col];
            #pragma unroll
            for (int mf = 0; mf < 2; mf++) {
                mma16(acc[mf][nf], ah[mf], bh0, bh1);
                mma16(acc[mf][nf], ah[mf], bl0, bl1);
                mma16(acc[mf][nf], al[mf], bh0, bh1);
            }
        }
        __syncthreads();
    }

    float* outb = g_qkv + b * O3C * N_;
    #pragma unroll
    for (int mf = 0; mf < 2; mf++) {
        int r = o0 + m_base + mf * 16 + gi;
        #pragma unroll
        for (int nf = 0; nf < 8; nf++) {
            int nc = n0 + n_base + nf * 8 + 2 * ti;
            *(float2*)&outb[r * N_ + nc]       = make_float2(acc[mf][nf][0], acc[mf][nf][1]);
            *(float2*)&outb[(r + 8) * N_ + nc] = make_float2(acc[mf][nf][2], acc[mf][nf][3]);
        }
    }
}

// ---------------------------------------------------------------------------
// Fused flash attention, tf32 mma. Block: 128 q rows, 8 warps (16 q each).
// TK chunk = 64. grid = (8, 6, 16).
// QP [128][68]: Q then P.  Kn [64 d][72]: K natural (coalesced fill,
// conflict-free B-frag reads: banks 8t+g).  Vh [64 d][68].
// ---------------------------------------------------------------------------
#define AST 68
#define KST 72
#define ATTN_SMEM ((128 * AST + 64 * KST + 64 * AST) * 4)

__global__ __launch_bounds__(256, 2) void attn_kernel(
    const unsigned char* __restrict__ mask_raw, float* __restrict__ out)
{
    extern __shared__ uint32_t As[];
    uint32_t* QP = As;                       // [128][AST]
    uint32_t* Kn = As + 128 * AST;           // [64][KST]  K: [d][m]
    uint32_t* Vh = Kn + 64 * KST;            // [64][AST]  V: [d][m]
    float*    Od = (float*)Kn;               // [64][132] output staging (reuse)

    const int q0 = blockIdx.x * 128;
    const int h  = blockIdx.y;
    const int b  = blockIdx.z;
    const int tid  = threadIdx.x;
    const int wid  = tid >> 5;
    const int lane = tid & 31;
    const int gi = lane >> 2;
    const int ti = lane & 3;
    const int wq = wid * 16;
    const int mode = g_mask_mode;

    const float sc2 = rsqrtf((float)C_) * 1.4426950408889634f;
    const float NEG = -1e30f;

    const float* qb = g_qkv + (b * O3C + h * D_) * N_;
    const float* kb = qb + C_ * N_;
    const float* vb = qb + 2 * C_ * N_;

    const int* mask_i32   = (const int*)mask_raw;
    const float* mask_f32 = (const float*)mask_raw;
    const int mbase = (b * HEADS_ + h) * N_ * N_;

    // ---- Load Q tile [128 q x 64 d], transposed, tf32 ----
    for (int e = tid; e < 128 * 64; e += 256) {
        int dd = e >> 7, qq = e & 127;
        QP[qq * AST + dd] = f2tf32(qb[dd * N_ + q0 + qq]);
    }
    __syncthreads();

    // ---- Cache Q A-fragments in registers ----
    uint32_t qa[8][4];
    #pragma unroll
    for (int ks = 0; ks < 8; ks++) {
        int r = wq + gi, c = ks * 8 + ti;
        qa[ks][0] = QP[r * AST + c];
        qa[ks][1] = QP[(r + 8) * AST + c];
        qa[ks][2] = QP[r * AST + c + 4];
        qa[ks][3] = QP[(r + 8) * AST + c + 4];
    }
    __syncthreads();

    float oa[8][4];
    #pragma unroll
    for (int nf = 0; nf < 8; nf++)
        #pragma unroll
        for (int k = 0; k < 4; k++) oa[nf][k] = 0.f;
    float m1 = NEG, m2 = NEG, l1 = 0.f, l2 = 0.f;

    const int r1g = q0 + wq + gi;

    for (int k0 = 0; k0 < N_; k0 += 64) {
        // ---- Fill K [d][m] and V [d][m], both coalesced float4 ----
        for (int e = tid; e < 1024; e += 256) {
            int dd = e >> 4, m4 = (e & 15) * 4;
            float4 kv = *(const float4*)&kb[dd * N_ + k0 + m4];
            *(uint4*)&Kn[dd * KST + m4] =
                make_uint4(f2tf32(kv.x), f2tf32(kv.y), f2tf32(kv.z), f2tf32(kv.w));
            float4 vv = *(const float4*)&vb[dd * N_ + k0 + m4];
            *(uint4*)&Vh[dd * AST + m4] =
                make_uint4(f2tf32(vv.x), f2tf32(vv.y), f2tf32(vv.z), f2tf32(vv.w));
        }
        __syncthreads();

        // ---- S = Q K^T : warp computes [16 x 64] ----
        float sa[8][4];
        #pragma unroll
        for (int nf = 0; nf < 8; nf++)
            #pragma unroll
            for (int k = 0; k < 4; k++) sa[nf][k] = 0.f;
        #pragma unroll
        for (int ks = 0; ks < 8; ks++) {
            #pragma unroll
            for (int nf = 0; nf < 8; nf++) {
                uint32_t b0 = Kn[(ks * 8 + ti) * KST + nf * 8 + gi];
                uint32_t b1 = Kn[(ks * 8 + ti + 4) * KST + nf * 8 + gi];
                mma8(sa[nf], qa[ks], b0, b1);
            }
        }

        // ---- scale + mask ----
        #pragma unroll
        for (int nf = 0; nf < 8; nf++) {
            int cb = k0 + nf * 8 + 2 * ti;
            int i1 = mbase + r1g * N_ + cb;
            int i2 = i1 + 8 * N_;
            bool k00, k01, k10, k11;
            if (mode == 0) {
                uchar2 a = *(const uchar2*)&mask_raw[i1];
                uchar2 c = *(const uchar2*)&mask_raw[i2];
                k00 = a.x; k01 = a.y; k10 = c.x; k11 = c.y;
            } else if (mode == 1) {
                int2 a = *(const int2*)&mask_i32[i1];
                int2 c = *(const int2*)&mask_i32[i2];
                k00 = a.x; k01 = a.y; k10 = c.x; k11 = c.y;
            } else {
                float2 a = *(const float2*)&mask_f32[i1];
                float2 c = *(const float2*)&mask_f32[i2];
                k00 = a.x != 0.f; k01 = a.y != 0.f; k10 = c.x != 0.f; k11 = c.y != 0.f;
            }
            sa[nf][0] = k00 ? NEG : sa[nf][0] * sc2;
            sa[nf][1] = k01 ? NEG : sa[nf][1] * sc2;
            sa[nf][2] = k10 ? NEG : sa[nf][2] * sc2;
            sa[nf][3] = k11 ? NEG : sa[nf][3] * sc2;
        }

        // ---- online softmax ----
        float mx1 = NEG, mx2 = NEG;
        #pragma unroll
        for (int nf = 0; nf < 8; nf++) {
            mx1 = fmaxf(mx1, fmaxf(sa[nf][0], sa[nf][1]));
            mx2 = fmaxf(mx2, fmaxf(sa[nf][2], sa[nf][3]));
        }
        mx1 = fmaxf(mx1, __shfl_xor_sync(0xffffffffu, mx1, 1));
        mx1 = fmaxf(mx1, __shfl_xor_sync(0xffffffffu, mx1, 2));
        mx2 = fmaxf(mx2, __shfl_xor_sync(0xffffffffu, mx2, 1));
        mx2 = fmaxf(mx2, __shfl_xor_sync(0xffffffffu, mx2, 2));
        float mn1 = fmaxf(m1, mx1), mn2 = fmaxf(m2, mx2);
        float corr1 = fexp2(m1 - mn1), corr2 = fexp2(m2 - mn2);

        float ls1 = 0.f, ls2 = 0.f;
        #pragma unroll
        for (int nf = 0; nf < 8; nf++) {
            float p00 = fexp2(sa[nf][0] - mn1);
            float p01 = fexp2(sa[nf][1] - mn1);
            float p10 = fexp2(sa[nf][2] - mn2);
            float p11 = fexp2(sa[nf][3] - mn2);
            ls1 += p00 + p01;
            ls2 += p10 + p11;
            int col = nf * 8 + 2 * ti;
            QP[(wq + gi) * AST + col]         = f2tf32(p00);
            QP[(wq + gi) * AST + col + 1]     = f2tf32(p01);
            QP[(wq + gi + 8) * AST + col]     = f2tf32(p10);
            QP[(wq + gi + 8) * AST + col + 1] = f2tf32(p11);
        }
        ls1 += __shfl_xor_sync(0xffffffffu, ls1, 1);
        ls1 += __shfl_xor_sync(0xffffffffu, ls1, 2);
        ls2 += __shfl_xor_sync(0xffffffffu, ls2, 1);
        ls2 += __shfl_xor_sync(0xffffffffu, ls2, 2);
        l1 = l1 * corr1 + ls1;
        l2 = l2 * corr2 + ls2;
        m1 = mn1; m2 = mn2;
        #pragma unroll
        for (int nf = 0; nf < 8; nf++) {
            oa[nf][0] *= corr1; oa[nf][1] *= corr1;
            oa[nf][2] *= corr2; oa[nf][3] *= corr2;
        }
        __syncwarp();

        // ---- O += P V ----
        #pragma unroll
        for (int kf = 0; kf < 8; kf++) {
            uint32_t pa[4];
            int r = wq + gi, c = kf * 8 + ti;
            pa[0] = QP[r * AST + c];
            pa[1] = QP[(r + 8) * AST + c];
            pa[2] = QP[r * AST + c + 4];
            pa[3] = QP[(r + 8) * AST + c + 4];
            #pragma unroll
            for (int nf = 0; nf < 8; nf++) {
                uint32_t b0 = Vh[(nf * 8 + gi) * AST + kf * 8 + ti];
                uint32_t b1 = Vh[(nf * 8 + gi) * AST + kf * 8 + ti + 4];
                mma8(oa[nf], pa, b0, b1);
            }
        }
        __syncthreads();
    }

    // ---- normalize + stage to smem [d][q] for coalesced output ----
    float il1 = 1.0f / l1, il2 = 1.0f / l2;
    #pragma unroll
    for (int nf = 0; nf < 8; nf++) {
        int d0 = nf * 8 + 2 * ti;
        Od[d0 * 132 + wq + gi]           = oa[nf][0] * il1;
        Od[(d0 + 1) * 132 + wq + gi]     = oa[nf][1] * il1;
        Od[d0 * 132 + wq + gi + 8]       = oa[nf][2] * il2;
        Od[(d0 + 1) * 132 + wq + gi + 8] = oa[nf][3] * il2;
    }
    __syncthreads();

    float* ob = out + (b * C_ + h * D_) * N_;
    for (int e = tid; e < 64 * 32; e += 256) {
        int dd = e >> 5, q4 = (e & 31) * 4;
        *(float4*)&ob[dd * N_ + q0 + q4] = *(const float4*)&Od[dd * 132 + q4];
    }
}

// ---------------------------------------------------------------------------
extern "C" void kernel_launch(void* const* d_in, const int* in_sizes, int n_in,
                              void* d_out, int out_size)
{
    const float* x         = (const float*)d_in[0];
    const float* w_qkv     = (const float*)d_in[1];
    const unsigned char* m = (const unsigned char*)d_in[2];
    float* out             = (float*)d_out;

    cudaFuncSetAttribute(attn_kernel,
                         cudaFuncAttributeMaxDynamicSharedMemorySize, ATTN_SMEM);

    detect_mask_kernel<<<1, 1024>>>((const uint4*)m);

    dim3 gemm_grid(N_ / 128, O3C / 128, B_);   // (8, 9, 16)
    qkv_gemm_kernel<<<gemm_grid, 256>>>(x, w_qkv);

    dim3 attn_grid(N_ / 128, HEADS_, B_);      // (8, 6, 16)
    attn_kernel<<<attn_grid, 256, ATTN_SMEM>>>(m, out);
}